// round 1
// baseline (speedup 1.0000x reference)
#include <cuda_runtime.h>
#include <cstdint>

// Problem constants (fixed by the reference)
#define NB   8192
#define EMB  768
#define NP   96
#define NK   256
#define ND   8

#define THREADS      128
#define ROWS_PER_T   4
#define ROWS_PER_BLK (THREADS * ROWS_PER_T)   // 512
#define GRID_X       (NB / ROWS_PER_BLK)      // 16

typedef unsigned long long u64;

__device__ __forceinline__ u64 ffma2(u64 a, u64 b, u64 c) {
    u64 d;
    asm("fma.rn.f32x2 %0, %1, %2, %3;" : "=l"(d) : "l"(a), "l"(b), "l"(c));
    return d;
}
__device__ __forceinline__ u64 pack2(float lo, float hi) {
    u64 r;
    asm("mov.b64 %0, {%1, %2};" : "=l"(r) : "f"(lo), "f"(hi));
    return r;
}
__device__ __forceinline__ void unpack2(u64 v, float& lo, float& hi) {
    asm("mov.b64 {%0, %1}, %2;" : "=f"(lo), "=f"(hi) : "l"(v));
}

__global__ __launch_bounds__(THREADS)
void pq_argmin_kernel(const float* __restrict__ vecs,
                      const float* __restrict__ codebook,
                      float* __restrict__ out) {
    // smem: per-code (-2c, -2c) duplicated float2 per dim, plus (||c||^2, ||c||^2)
    __shared__ __align__(16) float2 s_cdup[NK][ND];   // 16 KB
    __shared__ __align__(16) float2 s_c2[NK];         // 2 KB

    const int p   = blockIdx.y;
    const int tid = threadIdx.x;

    // ---- stage codebook[p] into smem (coalesced: 32B per code) ----
    for (int k = tid; k < NK; k += THREADS) {
        const float4* cb = reinterpret_cast<const float4*>(
            codebook + ((size_t)p * NK + k) * ND);
        float4 c0 = cb[0];
        float4 c1 = cb[1];
        float c2 = c0.x*c0.x + c0.y*c0.y + c0.z*c0.z + c0.w*c0.w
                 + c1.x*c1.x + c1.y*c1.y + c1.z*c1.z + c1.w*c1.w;
        s_cdup[k][0] = make_float2(-2.f*c0.x, -2.f*c0.x);
        s_cdup[k][1] = make_float2(-2.f*c0.y, -2.f*c0.y);
        s_cdup[k][2] = make_float2(-2.f*c0.z, -2.f*c0.z);
        s_cdup[k][3] = make_float2(-2.f*c0.w, -2.f*c0.w);
        s_cdup[k][4] = make_float2(-2.f*c1.x, -2.f*c1.x);
        s_cdup[k][5] = make_float2(-2.f*c1.y, -2.f*c1.y);
        s_cdup[k][6] = make_float2(-2.f*c1.z, -2.f*c1.z);
        s_cdup[k][7] = make_float2(-2.f*c1.w, -2.f*c1.w);
        s_c2[k]      = make_float2(c2, c2);
    }
    __syncthreads();

    // ---- load 4 rows' v-slices (each slice is exactly one 32B sector) ----
    const int rowBase = blockIdx.x * ROWS_PER_BLK;
    const int r0 = rowBase + tid;
    const int r1 = r0 + THREADS;
    const int r2 = r0 + 2 * THREADS;
    const int r3 = r0 + 3 * THREADS;

    float v0[ND], v1[ND], v2[ND], v3[ND];
    {
        const float4* g;
        g = reinterpret_cast<const float4*>(vecs + (size_t)r0 * EMB + p * ND);
        float4 a = g[0], b = g[1];
        v0[0]=a.x; v0[1]=a.y; v0[2]=a.z; v0[3]=a.w; v0[4]=b.x; v0[5]=b.y; v0[6]=b.z; v0[7]=b.w;
        g = reinterpret_cast<const float4*>(vecs + (size_t)r1 * EMB + p * ND);
        a = g[0]; b = g[1];
        v1[0]=a.x; v1[1]=a.y; v1[2]=a.z; v1[3]=a.w; v1[4]=b.x; v1[5]=b.y; v1[6]=b.z; v1[7]=b.w;
        g = reinterpret_cast<const float4*>(vecs + (size_t)r2 * EMB + p * ND);
        a = g[0]; b = g[1];
        v2[0]=a.x; v2[1]=a.y; v2[2]=a.z; v2[3]=a.w; v2[4]=b.x; v2[5]=b.y; v2[6]=b.z; v2[7]=b.w;
        g = reinterpret_cast<const float4*>(vecs + (size_t)r3 * EMB + p * ND);
        a = g[0]; b = g[1];
        v3[0]=a.x; v3[1]=a.y; v3[2]=a.z; v3[3]=a.w; v3[4]=b.x; v3[5]=b.y; v3[6]=b.z; v3[7]=b.w;
    }

    // pack rows pairwise for f32x2: (row0,row1) and (row2,row3)
    u64 v01[ND], v23[ND];
#pragma unroll
    for (int d = 0; d < ND; d++) {
        v01[d] = pack2(v0[d], v1[d]);
        v23[d] = pack2(v2[d], v3[d]);
    }

    float best0 = 3.4e38f, best1 = 3.4e38f, best2 = 3.4e38f, best3 = 3.4e38f;
    int   k0 = 0, k1 = 0, k2 = 0, k3 = 0;

    // ---- main argmin loop over 256 codes ----
#pragma unroll 4
    for (int k = 0; k < NK; k++) {
        const ulonglong2* cp = reinterpret_cast<const ulonglong2*>(&s_cdup[k][0]);
        ulonglong2 q0 = cp[0];   // d0, d1
        ulonglong2 q1 = cp[1];   // d2, d3
        ulonglong2 q2 = cp[2];   // d4, d5
        ulonglong2 q3 = cp[3];   // d6, d7
        u64 c2p = *reinterpret_cast<const u64*>(&s_c2[k]);

        u64 a01 = c2p, a23 = c2p;
        a01 = ffma2(v01[0], q0.x, a01);  a23 = ffma2(v23[0], q0.x, a23);
        a01 = ffma2(v01[1], q0.y, a01);  a23 = ffma2(v23[1], q0.y, a23);
        a01 = ffma2(v01[2], q1.x, a01);  a23 = ffma2(v23[2], q1.x, a23);
        a01 = ffma2(v01[3], q1.y, a01);  a23 = ffma2(v23[3], q1.y, a23);
        a01 = ffma2(v01[4], q2.x, a01);  a23 = ffma2(v23[4], q2.x, a23);
        a01 = ffma2(v01[5], q2.y, a01);  a23 = ffma2(v23[5], q2.y, a23);
        a01 = ffma2(v01[6], q3.x, a01);  a23 = ffma2(v23[6], q3.x, a23);
        a01 = ffma2(v01[7], q3.y, a01);  a23 = ffma2(v23[7], q3.y, a23);

        float s0, s1, s2, s3;
        unpack2(a01, s0, s1);
        unpack2(a23, s2, s3);

        // strict '<' keeps the lowest k on ties, matching jnp.argmax semantics
        if (s0 < best0) { best0 = s0; k0 = k; }
        if (s1 < best1) { best1 = s1; k1 = k; }
        if (s2 < best2) { best2 = s2; k2 = k; }
        if (s3 < best3) { best3 = s3; k3 = k; }
    }

    // ---- epilogue: gather winning code (c = (-2c) * -0.5 is bit-exact) ----
    {
        const float2* cr;
        float4 oa, ob;

        cr = s_cdup[k0];
        oa.x = -0.5f*cr[0].x; oa.y = -0.5f*cr[1].x; oa.z = -0.5f*cr[2].x; oa.w = -0.5f*cr[3].x;
        ob.x = -0.5f*cr[4].x; ob.y = -0.5f*cr[5].x; ob.z = -0.5f*cr[6].x; ob.w = -0.5f*cr[7].x;
        float4* o = reinterpret_cast<float4*>(out + (size_t)r0 * EMB + p * ND);
        o[0] = oa; o[1] = ob;

        cr = s_cdup[k1];
        oa.x = -0.5f*cr[0].x; oa.y = -0.5f*cr[1].x; oa.z = -0.5f*cr[2].x; oa.w = -0.5f*cr[3].x;
        ob.x = -0.5f*cr[4].x; ob.y = -0.5f*cr[5].x; ob.z = -0.5f*cr[6].x; ob.w = -0.5f*cr[7].x;
        o = reinterpret_cast<float4*>(out + (size_t)r1 * EMB + p * ND);
        o[0] = oa; o[1] = ob;

        cr = s_cdup[k2];
        oa.x = -0.5f*cr[0].x; oa.y = -0.5f*cr[1].x; oa.z = -0.5f*cr[2].x; oa.w = -0.5f*cr[3].x;
        ob.x = -0.5f*cr[4].x; ob.y = -0.5f*cr[5].x; ob.z = -0.5f*cr[6].x; ob.w = -0.5f*cr[7].x;
        o = reinterpret_cast<float4*>(out + (size_t)r2 * EMB + p * ND);
        o[0] = oa; o[1] = ob;

        cr = s_cdup[k3];
        oa.x = -0.5f*cr[0].x; oa.y = -0.5f*cr[1].x; oa.z = -0.5f*cr[2].x; oa.w = -0.5f*cr[3].x;
        ob.x = -0.5f*cr[4].x; ob.y = -0.5f*cr[5].x; ob.z = -0.5f*cr[6].x; ob.w = -0.5f*cr[7].x;
        o = reinterpret_cast<float4*>(out + (size_t)r3 * EMB + p * ND);
        o[0] = oa; o[1] = ob;
    }
}

extern "C" void kernel_launch(void* const* d_in, const int* in_sizes, int n_in,
                              void* d_out, int out_size) {
    const float* vecs     = (const float*)d_in[0];   // [8192, 768] f32
    const float* codebook = (const float*)d_in[1];   // [96, 256, 8] f32
    float* out            = (float*)d_out;           // [8192, 768] f32

    dim3 grid(GRID_X, NP);
    dim3 block(THREADS);
    pq_argmin_kernel<<<grid, block>>>(vecs, codebook, out);
}

// round 2
// speedup vs baseline: 1.3477x; 1.3477x over previous
#include <cuda_runtime.h>
#include <cstdint>
#include <cfloat>

// Problem constants (fixed by the reference)
#define NB   8192
#define EMB  768
#define NP   96
#define NK   256
#define ND   8
#define NKP  (NK / 2)        // 128 k-pairs

#define THREADS      128
#define ROWS_PER_T   4
#define ROWS_PER_BLK (THREADS * ROWS_PER_T)   // 512
#define GRID_X       (NB / ROWS_PER_BLK)      // 16

#define PAIR_STRIDE  10      // u64 per k-pair record (8 dims + c2 + pad)

typedef unsigned long long u64;

__device__ __forceinline__ u64 ffma2(u64 a, u64 b, u64 c) {
    u64 d;
    asm("fma.rn.f32x2 %0, %1, %2, %3;" : "=l"(d) : "l"(a), "l"(b), "l"(c));
    return d;
}
__device__ __forceinline__ u64 pack2(float lo, float hi) {
    u64 r;
    asm("mov.b64 %0, {%1, %2};" : "=l"(r) : "f"(lo), "f"(hi));
    return r;
}
__device__ __forceinline__ void unpack2(u64 v, float& lo, float& hi) {
    asm("mov.b64 {%0, %1}, %2;" : "=f"(lo), "=f"(hi) : "l"(v));
}

__global__ __launch_bounds__(THREADS, 4)
void pq_argmin_kernel(const float* __restrict__ vecs,
                      const float* __restrict__ codebook,
                      float* __restrict__ out) {
    // Per k-pair record: d0..d7 each packed as (-2*c_{2kp,d}, -2*c_{2kp+1,d}),
    // then (||c_2kp||^2, ||c_2kp+1||^2). Stride 10 u64 = 80B keeps 16B alignment.
    __shared__ __align__(16) u64 s_pair[NKP][PAIR_STRIDE];  // 10 KB

    const int p   = blockIdx.y;
    const int tid = threadIdx.x;

    // ---- stage codebook[p] into smem: one k-pair per thread ----
    {
        const int kp = tid;  // THREADS == NKP
        const float4* cb = reinterpret_cast<const float4*>(
            codebook + ((size_t)p * NK + 2 * kp) * ND);
        float4 a0 = cb[0], a1 = cb[1];   // code 2kp
        float4 b0 = cb[2], b1 = cb[3];   // code 2kp+1
        float c2a = a0.x*a0.x + a0.y*a0.y + a0.z*a0.z + a0.w*a0.w
                  + a1.x*a1.x + a1.y*a1.y + a1.z*a1.z + a1.w*a1.w;
        float c2b = b0.x*b0.x + b0.y*b0.y + b0.z*b0.z + b0.w*b0.w
                  + b1.x*b1.x + b1.y*b1.y + b1.z*b1.z + b1.w*b1.w;
        u64* rec = s_pair[kp];
        rec[0] = pack2(-2.f*a0.x, -2.f*b0.x);
        rec[1] = pack2(-2.f*a0.y, -2.f*b0.y);
        rec[2] = pack2(-2.f*a0.z, -2.f*b0.z);
        rec[3] = pack2(-2.f*a0.w, -2.f*b0.w);
        rec[4] = pack2(-2.f*a1.x, -2.f*b1.x);
        rec[5] = pack2(-2.f*a1.y, -2.f*b1.y);
        rec[6] = pack2(-2.f*a1.z, -2.f*b1.z);
        rec[7] = pack2(-2.f*a1.w, -2.f*b1.w);
        rec[8] = pack2(c2a, c2b);
    }
    __syncthreads();

    // ---- load 4 rows' v-slices (each slice is exactly one 32B sector) ----
    const int rowBase = blockIdx.x * ROWS_PER_BLK;
    int rows[ROWS_PER_T];
    rows[0] = rowBase + tid;
    rows[1] = rows[0] + THREADS;
    rows[2] = rows[0] + 2 * THREADS;
    rows[3] = rows[0] + 3 * THREADS;

    // v duplicated into both f32x2 lanes, per row per dim
    u64 vd[ROWS_PER_T][ND];
#pragma unroll
    for (int r = 0; r < ROWS_PER_T; r++) {
        const float4* g = reinterpret_cast<const float4*>(
            vecs + (size_t)rows[r] * EMB + p * ND);
        float4 a = g[0], b = g[1];
        vd[r][0] = pack2(a.x, a.x);
        vd[r][1] = pack2(a.y, a.y);
        vd[r][2] = pack2(a.z, a.z);
        vd[r][3] = pack2(a.w, a.w);
        vd[r][4] = pack2(b.x, b.x);
        vd[r][5] = pack2(b.y, b.y);
        vd[r][6] = pack2(b.z, b.z);
        vd[r][7] = pack2(b.w, b.w);
    }

    float best[ROWS_PER_T] = {FLT_MAX, FLT_MAX, FLT_MAX, FLT_MAX};
    int   idx [ROWS_PER_T] = {0, 0, 0, 0};

    // ---- main argmin loop: 128 steps, 2 codes per step ----
#pragma unroll 2
    for (int s = 0; s < NKP; s++) {
        const u64* rec = s_pair[s];
        const ulonglong2* rp = reinterpret_cast<const ulonglong2*>(rec);
        ulonglong2 q0 = rp[0];   // dims 0,1
        ulonglong2 q1 = rp[1];   // dims 2,3
        ulonglong2 q2 = rp[2];   // dims 4,5
        ulonglong2 q3 = rp[3];   // dims 6,7
        u64 c2p = rec[8];

#pragma unroll
        for (int r = 0; r < ROWS_PER_T; r++) {
            u64 acc = c2p;
            acc = ffma2(vd[r][0], q0.x, acc);
            acc = ffma2(vd[r][1], q0.y, acc);
            acc = ffma2(vd[r][2], q1.x, acc);
            acc = ffma2(vd[r][3], q1.y, acc);
            acc = ffma2(vd[r][4], q2.x, acc);
            acc = ffma2(vd[r][5], q2.y, acc);
            acc = ffma2(vd[r][6], q3.x, acc);
            acc = ffma2(vd[r][7], q3.y, acc);
            float sa, sb;
            unpack2(acc, sa, sb);

            // strict '<' keeps lowest k on exact ties (matches jnp.argmax)
            bool  pa   = sb < sa;                 // tie -> even (lower) k
            float smin = fminf(sa, sb);
            int   kc   = 2 * s + (pa ? 1 : 0);
            bool  pb   = smin < best[r];          // tie -> keep earlier k
            best[r] = fminf(best[r], smin);       // FMNMX: short dep chain
            if (pb) idx[r] = kc;
        }
    }

    // ---- epilogue: gather winning code; c = (-2c) * -0.5 is bit-exact ----
#pragma unroll
    for (int r = 0; r < ROWS_PER_T; r++) {
        int k = idx[r];
        const float* h = reinterpret_cast<const float*>(s_pair[k >> 1]) + (k & 1);
        float4 oa, ob;
        oa.x = -0.5f * h[0];
        oa.y = -0.5f * h[2];
        oa.z = -0.5f * h[4];
        oa.w = -0.5f * h[6];
        ob.x = -0.5f * h[8];
        ob.y = -0.5f * h[10];
        ob.z = -0.5f * h[12];
        ob.w = -0.5f * h[14];
        float4* o = reinterpret_cast<float4*>(out + (size_t)rows[r] * EMB + p * ND);
        o[0] = oa;
        o[1] = ob;
    }
}

extern "C" void kernel_launch(void* const* d_in, const int* in_sizes, int n_in,
                              void* d_out, int out_size) {
    const float* vecs     = (const float*)d_in[0];   // [8192, 768] f32
    const float* codebook = (const float*)d_in[1];   // [96, 256, 8] f32
    float* out            = (float*)d_out;           // [8192, 768] f32

    dim3 grid(GRID_X, NP);
    dim3 block(THREADS);
    pq_argmin_kernel<<<grid, block>>>(vecs, codebook, out);
}